// round 3
// baseline (speedup 1.0000x reference)
#include <cuda_runtime.h>
#include <cuda_bf16.h>
#include <cstdint>

// ---------------------------------------------------------------------------
// SPMoEAdaptor: out = moe_b(moe_a(x)) + x
//   moe(x) = sum_e softmax(x@Wg)[:,e] * ((x - b_e) @ W_e)
//          = sum_e (g_e * x) @ W_e  -  sum_e g_e * (b_e @ W_e)
// Implementation: warp-level mma.sync m16n8k16 bf16 (baseline PTX, works at
// .target sm_103). Gates applied to A-fragments pre-MMA so experts become
// extra K (M=128, N=64, K=4*64 per layer) and accumulators fit in registers.
// fp32 gates(A), fp32 residual, fp32 epilogue folds.
// ---------------------------------------------------------------------------

namespace {
constexpr int MT = 128;                 // tokens per tile

// dynamic smem layout (bytes)
constexpr int SM_X   = 0;               // 128 rows x 128B bf16 (16B-chunk XOR swizzle)
constexpr int SM_WA  = 16384;           // 256 rows x 128B bf16 (layer A weights, swizzled)
constexpr int SM_WB  = 49152;           // layer B weights
constexpr int SM_GA  = 81920;           // 128 x float4 gates(A)
constexpr int SM_WGA = 83968;           // 64 x float4  (w_gate_a as [d][e])
constexpr int SM_WGB = 84992;
constexpr int SM_CA  = 86016;           // 64 x float4  (c_a as [f][e])
constexpr int SM_CB  = 87040;
constexpr int SMEM_TOTAL = 88064;

constexpr int GRID = 592;               // = 148 SMs * 2 CTAs/SM * 2 waves
}

// device-global scratch (allocation-free rule)
__device__ __align__(16) __nv_bfloat16 g_wswz[2][256 * 64]; // pre-swizzled bf16 W images
__device__ __align__(16) float g_c[2][64 * 4];              // c[L][f*4+e] = (b_e @ W_e)[f]

// ------------------------------- helpers ----------------------------------

__device__ __forceinline__ uint32_t smem_u32(const void* p) {
    uint32_t a;
    asm("{ .reg .u64 t; cvta.to.shared.u64 t, %1; cvt.u32.u64 %0, t; }" : "=r"(a) : "l"(p));
    return a;
}

__device__ __forceinline__ void sts128(uint32_t addr, uint32_t a, uint32_t b,
                                       uint32_t c, uint32_t d) {
    asm volatile("st.shared.v4.b32 [%0], {%1, %2, %3, %4};"
                 :: "r"(addr), "r"(a), "r"(b), "r"(c), "r"(d) : "memory");
}

__device__ __forceinline__ void ldsm_x4(uint32_t* r, uint32_t addr) {
    asm volatile("ldmatrix.sync.aligned.m8n8.x4.shared.b16 {%0,%1,%2,%3}, [%4];"
                 : "=r"(r[0]), "=r"(r[1]), "=r"(r[2]), "=r"(r[3]) : "r"(addr));
}

__device__ __forceinline__ void ldsm_x4_t(uint32_t* r, uint32_t addr) {
    asm volatile("ldmatrix.sync.aligned.m8n8.x4.trans.shared.b16 {%0,%1,%2,%3}, [%4];"
                 : "=r"(r[0]), "=r"(r[1]), "=r"(r[2]), "=r"(r[3]) : "r"(addr));
}

__device__ __forceinline__ void mma_bf16(float* d, const uint32_t* a,
                                         uint32_t b0, uint32_t b1) {
    asm volatile("mma.sync.aligned.m16n8k16.row.col.f32.bf16.bf16.f32 "
                 "{%0,%1,%2,%3}, {%4,%5,%6,%7}, {%8,%9}, {%0,%1,%2,%3};"
                 : "+f"(d[0]), "+f"(d[1]), "+f"(d[2]), "+f"(d[3])
                 : "r"(a[0]), "r"(a[1]), "r"(a[2]), "r"(a[3]), "r"(b0), "r"(b1));
}

__device__ __forceinline__ uint32_t pack_bf2(float lo, float hi) {
    __nv_bfloat162 t = __floats2bfloat162_rn(lo, hi);
    return *reinterpret_cast<uint32_t*>(&t);
}

__device__ __forceinline__ uint32_t bf2bcast(float v) { return pack_bf2(v, v); }

__device__ __forceinline__ uint32_t hmul2u(uint32_t a, uint32_t b) {
    __nv_bfloat162 r = __hmul2(*reinterpret_cast<__nv_bfloat162*>(&a),
                               *reinterpret_cast<__nv_bfloat162*>(&b));
    return *reinterpret_cast<uint32_t*>(&r);
}

__device__ __forceinline__ float dot4(float4 a, float4 b) {
    return a.x * b.x + a.y * b.y + a.z * b.z + a.w * b.w;
}

__device__ __forceinline__ float4 softmax4(float4 l) {
    float mx = fmaxf(fmaxf(l.x, l.y), fmaxf(l.z, l.w));
    float e0 = __expf(l.x - mx), e1 = __expf(l.y - mx),
          e2 = __expf(l.z - mx), e3 = __expf(l.w - mx);
    float inv = 1.f / (e0 + e1 + e2 + e3);
    return make_float4(e0 * inv, e1 * inv, e2 * inv, e3 * inv);
}

// one MoE GEMM layer: acc[2][8][4] += sum over e,kt of (g_e o A_frag) @ W_frag
__device__ __forceinline__ void run_layer(float acc[2][8][4],
                                          const uint32_t xf[2][4][4],
                                          const uint32_t g2[4][2][2],
                                          uint32_t wbase, int lane) {
    const int lr = lane & 15;
    const int hi = lane >> 4;
    const int l7 = lane & 7;
    #pragma unroll
    for (int e = 0; e < 4; e++) {
        #pragma unroll
        for (int kt = 0; kt < 4; kt++) {
            uint32_t a[2][4];
            #pragma unroll
            for (int m = 0; m < 2; m++) {
                a[m][0] = hmul2u(xf[m][kt][0], g2[e][m][0]);
                a[m][1] = hmul2u(xf[m][kt][1], g2[e][m][1]);
                a[m][2] = hmul2u(xf[m][kt][2], g2[e][m][0]);
                a[m][3] = hmul2u(xf[m][kt][3], g2[e][m][1]);
            }
            const uint32_t r = (uint32_t)(e * 64 + kt * 16 + lr);
            #pragma unroll
            for (int np = 0; np < 4; np++) {
                uint32_t chunk = (uint32_t)((np * 2 + hi) ^ l7);
                uint32_t b[4];
                ldsm_x4_t(b, wbase + r * 128u + chunk * 16u);
                #pragma unroll
                for (int m = 0; m < 2; m++) {
                    mma_bf16(acc[m][2 * np],     a[m], b[0], b[1]);
                    mma_bf16(acc[m][2 * np + 1], a[m], b[2], b[3]);
                }
            }
        }
    }
}

// ------------------------------- prep kernel ------------------------------

__global__ void prep_kernel(const float* __restrict__ wea, const float* __restrict__ bea,
                            const float* __restrict__ web, const float* __restrict__ beb) {
    int idx = blockIdx.x * blockDim.x + threadIdx.x;
    if (idx < 2 * 4 * 64 * 64) {
        int L = idx >> 14;
        int r = idx & 16383;
        int e = r >> 12;
        int d = (r >> 6) & 63;
        int f = r & 63;
        const float* w = L ? web : wea;
        float v = w[(e * 64 + d) * 64 + f];
        int row = e * 64 + d;                       // K-index row
        int chunk = (f >> 3) ^ (d & 7);             // 16B-chunk XOR swizzle
        g_wswz[L][row * 64 + chunk * 8 + (f & 7)] = __float2bfloat16(v);
    }
    if (idx < 2 * 4 * 64) {
        int L = idx >> 8;
        int e = (idx >> 6) & 3;
        int f = idx & 63;
        const float* w = L ? web : wea;
        const float* b = L ? beb : bea;
        float s = 0.f;
        for (int d = 0; d < 64; d++)
            s += b[e * 64 + d] * w[(e * 64 + d) * 64 + f];
        g_c[L][f * 4 + e] = s;
    }
}

// ------------------------------- main kernel ------------------------------

__global__ void __launch_bounds__(128, 2)
moe_kernel(const float* __restrict__ x,
           const float* __restrict__ wg_a,
           const float* __restrict__ wg_b,
           float* __restrict__ out,
           int ntiles) {
    extern __shared__ char smem[];
    const uint32_t sb = smem_u32(smem);
    const int tid  = threadIdx.x;
    const int lane = tid & 31;
    const int warp = tid >> 5;
    const int rbase = warp * 32;

    // ---- one-time cooperative weight copies ----
    {
        const uint4* s0 = reinterpret_cast<const uint4*>(g_wswz[0]);
        const uint4* s1 = reinterpret_cast<const uint4*>(g_wswz[1]);
        uint4* dA = reinterpret_cast<uint4*>(smem + SM_WA);
        uint4* dB = reinterpret_cast<uint4*>(smem + SM_WB);
        #pragma unroll
        for (int i = tid; i < 2048; i += 128) { dA[i] = s0[i]; dB[i] = s1[i]; }
        float* wga_s = reinterpret_cast<float*>(smem + SM_WGA);
        float* wgb_s = reinterpret_cast<float*>(smem + SM_WGB);
        float* ca_s  = reinterpret_cast<float*>(smem + SM_CA);
        float* cb_s  = reinterpret_cast<float*>(smem + SM_CB);
        #pragma unroll
        for (int i = tid; i < 256; i += 128) {
            wga_s[i] = wg_a[i]; wgb_s[i] = wg_b[i];
            ca_s[i]  = g_c[0][i]; cb_s[i] = g_c[1][i];
        }
    }
    __syncthreads();

    const float4* WGA4 = reinterpret_cast<const float4*>(smem + SM_WGA);
    const float4* WGB4 = reinterpret_cast<const float4*>(smem + SM_WGB);
    const float4* CA4  = reinterpret_cast<const float4*>(smem + SM_CA);
    const float4* CB4  = reinterpret_cast<const float4*>(smem + SM_CB);

    for (int tile = blockIdx.x; tile < ntiles; tile += gridDim.x) {
        const size_t tokbase = (size_t)tile * MT;

        __syncwarp();   // protect X tile from previous-iteration readers

        // ---- load own token row fp32 ----
        float xrow[64];
        {
            const float4* xin = reinterpret_cast<const float4*>(x + (tokbase + tid) * 64);
            #pragma unroll
            for (int i = 0; i < 16; i++) {
                float4 v = xin[i];
                xrow[4*i] = v.x; xrow[4*i+1] = v.y; xrow[4*i+2] = v.z; xrow[4*i+3] = v.w;
            }
        }
        // ---- write bf16 X tile (swizzled) ----
        #pragma unroll
        for (int j = 0; j < 8; j++) {
            uint32_t p0 = pack_bf2(xrow[8*j+0], xrow[8*j+1]);
            uint32_t p1 = pack_bf2(xrow[8*j+2], xrow[8*j+3]);
            uint32_t p2 = pack_bf2(xrow[8*j+4], xrow[8*j+5]);
            uint32_t p3 = pack_bf2(xrow[8*j+6], xrow[8*j+7]);
            uint32_t off = (uint32_t)tid * 128u + (uint32_t)((j ^ (tid & 7)) * 16);
            sts128(sb + SM_X + off, p0, p1, p2, p3);
        }
        // ---- gates A (exact fp32) ----
        {
            float4 l = make_float4(0.f, 0.f, 0.f, 0.f);
            #pragma unroll
            for (int d = 0; d < 64; d++) {
                float4 w = WGA4[d];
                l.x = fmaf(xrow[d], w.x, l.x); l.y = fmaf(xrow[d], w.y, l.y);
                l.z = fmaf(xrow[d], w.z, l.z); l.w = fmaf(xrow[d], w.w, l.w);
            }
            *reinterpret_cast<float4*>(smem + SM_GA + tid * 16) = softmax4(l);
        }
        __syncwarp();

        // ---- per-row gate vectors (rows this lane owns in the MMA layout) ----
        float4 gAf[2][2];
        uint32_t gA2[4][2][2];
        #pragma unroll
        for (int m = 0; m < 2; m++) {
            int rl = rbase + m * 16 + (lane >> 2);
            gAf[m][0] = *reinterpret_cast<const float4*>(smem + SM_GA + rl * 16);
            gAf[m][1] = *reinterpret_cast<const float4*>(smem + SM_GA + (rl + 8) * 16);
            #pragma unroll
            for (int h = 0; h < 2; h++) {
                float4 g = gAf[m][h];
                gA2[0][m][h] = bf2bcast(g.x); gA2[1][m][h] = bf2bcast(g.y);
                gA2[2][m][h] = bf2bcast(g.z); gA2[3][m][h] = bf2bcast(g.w);
            }
        }

        // ---- X fragments ----
        uint32_t xf[2][4][4];
        #pragma unroll
        for (int m = 0; m < 2; m++)
            #pragma unroll
            for (int kt = 0; kt < 4; kt++) {
                uint32_t R = (uint32_t)(rbase + m * 16 + (lane & 15));
                uint32_t chunk = (uint32_t)((2 * kt + (lane >> 4)) ^ (lane & 7));
                ldsm_x4(xf[m][kt], sb + SM_X + R * 128u + chunk * 16u);
            }

        float acc[2][8][4];
        #pragma unroll
        for (int m = 0; m < 2; m++)
            #pragma unroll
            for (int n = 0; n < 8; n++)
                #pragma unroll
                for (int k = 0; k < 4; k++) acc[m][n][k] = 0.f;

        run_layer(acc, xf, gA2, sb + SM_WA, lane);

        __syncwarp();   // frags consumed; safe to overwrite X with h

        // ---- epilogue A: h = acc - sum_e g_e c_a ; write h bf16 back to X ----
        #pragma unroll
        for (int m = 0; m < 2; m++) {
            int rl = rbase + m * 16 + (lane >> 2);
            int rh = rl + 8;
            #pragma unroll
            for (int n = 0; n < 8; n++) {
                int c = n * 8 + (lane & 3) * 2;
                float4 c0 = CA4[c], c1 = CA4[c + 1];
                acc[m][n][0] -= dot4(gAf[m][0], c0);
                acc[m][n][1] -= dot4(gAf[m][0], c1);
                acc[m][n][2] -= dot4(gAf[m][1], c0);
                acc[m][n][3] -= dot4(gAf[m][1], c1);
                uint32_t offl = (uint32_t)rl * 128u +
                                (uint32_t)((((c >> 3) ^ (rl & 7)) * 16) + (c & 7) * 2);
                uint32_t offh = (uint32_t)rh * 128u +
                                (uint32_t)((((c >> 3) ^ (rh & 7)) * 16) + (c & 7) * 2);
                asm volatile("st.shared.b32 [%0], %1;"
                             :: "r"(sb + SM_X + offl), "r"(pack_bf2(acc[m][n][0], acc[m][n][1])) : "memory");
                asm volatile("st.shared.b32 [%0], %1;"
                             :: "r"(sb + SM_X + offh), "r"(pack_bf2(acc[m][n][2], acc[m][n][3])) : "memory");
            }
        }

        // ---- gates B from fp32 h via shfl reduction over lane%4 group ----
        float4 lg[2][2];
        #pragma unroll
        for (int m = 0; m < 2; m++)
            #pragma unroll
            for (int h = 0; h < 2; h++) lg[m][h] = make_float4(0.f, 0.f, 0.f, 0.f);
        #pragma unroll
        for (int n = 0; n < 8; n++) {
            int c = n * 8 + (lane & 3) * 2;
            float4 w0 = WGB4[c], w1 = WGB4[c + 1];
            #pragma unroll
            for (int m = 0; m < 2; m++)
                #pragma unroll
                for (int h = 0; h < 2; h++) {
                    float v0 = acc[m][n][h * 2], v1 = acc[m][n][h * 2 + 1];
                    lg[m][h].x += v0 * w0.x + v1 * w1.x;
                    lg[m][h].y += v0 * w0.y + v1 * w1.y;
                    lg[m][h].z += v0 * w0.z + v1 * w1.z;
                    lg[m][h].w += v0 * w0.w + v1 * w1.w;
                }
        }
        float4 gBf[2][2];
        uint32_t gB2[4][2][2];
        #pragma unroll
        for (int m = 0; m < 2; m++)
            #pragma unroll
            for (int h = 0; h < 2; h++) {
                float4 v = lg[m][h];
                v.x += __shfl_xor_sync(0xffffffffu, v.x, 1);
                v.y += __shfl_xor_sync(0xffffffffu, v.y, 1);
                v.z += __shfl_xor_sync(0xffffffffu, v.z, 1);
                v.w += __shfl_xor_sync(0xffffffffu, v.w, 1);
                v.x += __shfl_xor_sync(0xffffffffu, v.x, 2);
                v.y += __shfl_xor_sync(0xffffffffu, v.y, 2);
                v.z += __shfl_xor_sync(0xffffffffu, v.z, 2);
                v.w += __shfl_xor_sync(0xffffffffu, v.w, 2);
                float4 g = softmax4(v);
                gBf[m][h] = g;
                gB2[0][m][h] = bf2bcast(g.x); gB2[1][m][h] = bf2bcast(g.y);
                gB2[2][m][h] = bf2bcast(g.z); gB2[3][m][h] = bf2bcast(g.w);
            }

        __syncwarp();   // h tile visible to whole warp

        // ---- h fragments, layer B ----
        #pragma unroll
        for (int m = 0; m < 2; m++)
            #pragma unroll
            for (int kt = 0; kt < 4; kt++) {
                uint32_t R = (uint32_t)(rbase + m * 16 + (lane & 15));
                uint32_t chunk = (uint32_t)((2 * kt + (lane >> 4)) ^ (lane & 7));
                ldsm_x4(xf[m][kt], sb + SM_X + R * 128u + chunk * 16u);
            }
        #pragma unroll
        for (int m = 0; m < 2; m++)
            #pragma unroll
            for (int n = 0; n < 8; n++)
                #pragma unroll
                for (int k = 0; k < 4; k++) acc[m][n][k] = 0.f;

        run_layer(acc, xf, gB2, sb + SM_WB, lane);

        // ---- epilogue B: out = acc - sum_e g_e c_b + x (residual, fp32) ----
        #pragma unroll
        for (int m = 0; m < 2; m++) {
            size_t rl = tokbase + (size_t)(rbase + m * 16 + (lane >> 2));
            size_t rh = rl + 8;
            #pragma unroll
            for (int n = 0; n < 8; n++) {
                int c = n * 8 + (lane & 3) * 2;
                float4 c0 = CB4[c], c1 = CB4[c + 1];
                float2 xl = *reinterpret_cast<const float2*>(x + rl * 64 + c);
                float2 xh = *reinterpret_cast<const float2*>(x + rh * 64 + c);
                float2 ol, oh;
                ol.x = acc[m][n][0] - dot4(gBf[m][0], c0) + xl.x;
                ol.y = acc[m][n][1] - dot4(gBf[m][0], c1) + xl.y;
                oh.x = acc[m][n][2] - dot4(gBf[m][1], c0) + xh.x;
                oh.y = acc[m][n][3] - dot4(gBf[m][1], c1) + xh.y;
                *reinterpret_cast<float2*>(out + rl * 64 + c) = ol;
                *reinterpret_cast<float2*>(out + rh * 64 + c) = oh;
            }
        }
    }
}

// ------------------------------- launch -----------------------------------

extern "C" void kernel_launch(void* const* d_in, const int* in_sizes, int n_in,
                              void* d_out, int out_size) {
    const float* x   = (const float*)d_in[0];
    const float* wga = (const float*)d_in[1];
    const float* wea = (const float*)d_in[2];
    const float* bea = (const float*)d_in[3];
    const float* wgb = (const float*)d_in[4];
    const float* web = (const float*)d_in[5];
    const float* beb = (const float*)d_in[6];
    float* out = (float*)d_out;

    const int ntok   = in_sizes[0] / 64;
    const int ntiles = ntok / MT;

    prep_kernel<<<64, 512>>>(wea, bea, web, beb);

    cudaFuncSetAttribute(moe_kernel, cudaFuncAttributeMaxDynamicSharedMemorySize, SMEM_TOTAL);
    int grid = ntiles < GRID ? ntiles : GRID;
    moe_kernel<<<grid, 128, SMEM_TOTAL>>>(x, wga, wgb, out, ntiles);
}